// round 15
// baseline (speedup 1.0000x reference)
#include <cuda_runtime.h>

// ============================================================================
// AdderNet TauNet R15: R14 + min-identity:  sum|a-w| = A + W - 2*sum min(a,w)
// -> per tap 1 FMNMX (alu) + 1 FADD (fma) instead of 2 FADD (fma).
// Window sums shared per position; weight sums folded into BN beta.
// ============================================================================

#define EPSV 1e-5f

// ---- s_small layout (floats), compact ----
#define W1OFF   0      // 5 x 16
#define W2OFF   80     // 50 x 12
#define R1TOFF  680    // 10ci x 16
#define R2TOFF  840    // 10ci x 16
#define A1OFF   1000
#define B1OFF   1005
#define A2OFF   1010
#define B2OFF   1020
#define AR1OFF  1030
#define BR1OFF  1040
#define AR2OFF  1050
#define BR2OFF  1060
#define AOAOFF  1070   // 140
#define BOAOFF  1210   // 140
#define AOBOFF  1350   // 60
#define BOBOFF  1410   // 60
#define AOCOFF  1470   // 2
#define BOCOFF  1472   // 2
#define QOCOFF  1474   // 64
#define SMALL_N 1540

// per-channel quantized-weight sums (for beta folding at CTA start)
#define W1S 0
#define W2S 5
#define R1S 15
#define R2S 25
#define OAS 35
#define OBS 175
#define NSUM 235

__device__ float g_small[1544];
__device__ float g_wsum[240];
__device__ float g_qoa[2 * 35 * 70 * 4];   // [branch][i/4][c][4]
__device__ float g_qob[2 * 18 * 30 * 4];

__device__ __forceinline__ float quantv(float w, float s) {
    float t = fminf(fmaxf(w / s, -127.f), 127.f);
    return rintf(t) * s;
}

__device__ __forceinline__ void fill_bn(const float* bn, int c, float* A, float* Bt) {
    for (int i = threadIdx.x; i < c; i += blockDim.x) {
        float g = bn[i], b = bn[c + i], m = bn[2 * c + i], v = bn[3 * c + i];
        float al = g * rsqrtf(v + EPSV);
        A[i] = al;
        Bt[i] = b - m * al;
    }
}

// ---------------------------------------------------------------------------
__global__ void setup_kernel(
    const float* __restrict__ w1,   const float* __restrict__ w2,
    const float* __restrict__ wr1,  const float* __restrict__ wr2,
    const float* __restrict__ wo1a, const float* __restrict__ wo1b, const float* __restrict__ wo1c,
    const float* __restrict__ wo2a, const float* __restrict__ wo2b, const float* __restrict__ wo2c,
    const float* __restrict__ bn1,  const float* __restrict__ bn2,
    const float* __restrict__ bnr1, const float* __restrict__ bnr2,
    const float* __restrict__ bno1a, const float* __restrict__ bno1b, const float* __restrict__ bno1c,
    const float* __restrict__ bno2a, const float* __restrict__ bno2b, const float* __restrict__ bno2c)
{
    const int blk = blockIdx.x, tid = threadIdx.x;
    if (blk < 10) {
        const float* w; int n;
        switch (blk) {
            case 0: w = w1;   n = 65;   break;
            case 1: w = w2;   n = 450;  break;
            case 2: w = wr1;  n = 100;  break;
            case 3: w = wr2;  n = 100;  break;
            case 4: w = wo1a; n = 9800; break;
            case 5: w = wo2a; n = 9800; break;
            case 6: w = wo1b; n = 2100; break;
            case 7: w = wo2b; n = 2100; break;
            case 8: w = wo1c; n = 30;   break;
            default: w = wo2c; n = 30;  break;
        }
        __shared__ float red[256];
        float m = 0.f;
        for (int i = tid; i < n; i += 256) m = fmaxf(m, fabsf(w[i]));
        red[tid] = m;
        __syncthreads();
        for (int s = 128; s > 0; s >>= 1) {
            if (tid < s) red[tid] = fmaxf(red[tid], red[tid + s]);
            __syncthreads();
        }
        const float s = red[0] / 127.f;

        if (blk == 0) {
            for (int j = tid; j < 80; j += 256) {
                int c = j >> 4, k = j & 15;
                g_small[W1OFF + j] = (k < 13) ? quantv(w[c * 13 + k], s) : 0.f;
            }
            if (tid < 5) {
                float sm = 0.f;
                for (int k = 0; k < 13; k++) sm += quantv(w[tid * 13 + k], s);
                g_wsum[W1S + tid] = sm;
            }
        } else if (blk == 1) {
            for (int j = tid; j < 600; j += 256) {
                int row = j / 12, k = j - row * 12;
                g_small[W2OFF + j] = (k < 9) ? quantv(w[row * 9 + k], s) : 0.f;
            }
            if (tid < 10) {
                float sm = 0.f;
                for (int i = 0; i < 45; i++) sm += quantv(w[tid * 45 + i], s);
                g_wsum[W2S + tid] = sm;
            }
        } else if (blk == 2 || blk == 3) {
            float* dst = g_small + (blk == 2 ? R1TOFF : R2TOFF);
            for (int j = tid; j < 160; j += 256) {
                int ci = j >> 4, rem = j & 15;
                int g = rem >> 3, k = rem & 7;
                int c = 5 * g + k;
                dst[j] = (k < 5) ? quantv(w[c * 10 + ci], s) : 0.f;
            }
            if (tid < 10) {
                float sm = 0.f;
                for (int ci = 0; ci < 10; ci++) sm += quantv(w[tid * 10 + ci], s);
                g_wsum[(blk == 2 ? R1S : R2S) + tid] = sm;
            }
        } else if (blk == 4 || blk == 5) {
            float* dst = g_qoa + (blk - 4) * 9800;
            for (int j = tid; j < 9800; j += 256) {
                int i4 = j / 280, rem = j - i4 * 280;
                int c = rem >> 2, t = rem & 3;
                dst[j] = quantv(w[c * 140 + i4 * 4 + t], s);
            }
            if (tid < 70) {
                float sm = 0.f;
                for (int i = 0; i < 140; i++) sm += quantv(w[tid * 140 + i], s);
                g_wsum[OAS + (blk - 4) * 70 + tid] = sm;
            }
        } else if (blk == 6 || blk == 7) {
            float* dst = g_qob + (blk - 6) * 2160;
            for (int j = tid; j < 2160; j += 256) {
                int i4 = j / 120, rem = j - i4 * 120;
                int c = rem >> 2, t = rem & 3;
                int i = i4 * 4 + t;
                dst[j] = (i < 70) ? quantv(w[c * 70 + i], s) : 0.f;
            }
            if (tid < 30) {
                float sm = 0.f;
                for (int i = 0; i < 70; i++) sm += quantv(w[tid * 70 + i], s);
                g_wsum[OBS + (blk - 6) * 30 + tid] = sm;
            }
        } else {
            float* dst = g_small + QOCOFF + (blk - 8) * 32;
            if (tid < 32) dst[tid] = (tid < 30) ? quantv(w[tid], s) : 0.f;
        }
    } else {
        fill_bn(bn1, 5,  g_small + A1OFF,  g_small + B1OFF);
        fill_bn(bn2, 10, g_small + A2OFF,  g_small + B2OFF);
        fill_bn(bnr1, 10, g_small + AR1OFF, g_small + BR1OFF);
        fill_bn(bnr2, 10, g_small + AR2OFF, g_small + BR2OFF);
        fill_bn(bno1a, 70, g_small + AOAOFF,      g_small + BOAOFF);
        fill_bn(bno2a, 70, g_small + AOAOFF + 70, g_small + BOAOFF + 70);
        fill_bn(bno1b, 30, g_small + AOBOFF,      g_small + BOBOFF);
        fill_bn(bno2b, 30, g_small + AOBOFF + 30, g_small + BOBOFF + 30);
        fill_bn(bno1c, 1, g_small + AOCOFF,     g_small + BOCOFF);
        fill_bn(bno2c, 1, g_small + AOCOFF + 1, g_small + BOCOFF + 1);
    }
}

// ---------------------------------------------------------------------------
// Per-warp workspace (floats). Activations float4 = (e0,e1,e2,e3).
//   X  @0     float4[256] (1024)   [T aliases X; A aliases X; SW/RS @ X4+160+]
//   H1 @1024  float4[245] (980)    [F aliases H1]
//   H2 @2004  float4[144] (576)    [SX during pre1; B aliases H2]
#define XOFF  0
#define H1OFF 1024
#define H2OFF 2004
#define FOFF  1024
#define AOFF  0
#define BOFF  2004
#define WS_N  2580

__device__ __forceinline__ void ld4(float* d, const float* s) {
    float4 v = *(const float4*)s;
    d[0] = v.x; d[1] = v.y; d[2] = v.z; d[3] = v.w;
}

// acc += min(u, w) per component: FMNMX (alu) + FADD (fma)
__device__ __forceinline__ void accm4(float4& a, float4 u, float w) {
    a.x += fminf(u.x, w);
    a.y += fminf(u.y, w);
    a.z += fminf(u.z, w);
    a.w += fminf(u.w, w);
}

__device__ __forceinline__ float4 add4(float4 a, float4 b) {
    return make_float4(a.x + b.x, a.y + b.y, a.z + b.z, a.w + b.w);
}

// v = 2*S - A
__device__ __forceinline__ float4 v2sa(float4 S, float4 A) {
    return make_float4(fmaf(2.f, S.x, -A.x), fmaf(2.f, S.y, -A.y),
                       fmaf(2.f, S.z, -A.z), fmaf(2.f, S.w, -A.w));
}

// relu(v*al + be2)
__device__ __forceinline__ float4 bnrelu4p(float4 v, float al, float be) {
    return make_float4(fmaxf(fmaf(v.x, al, be), 0.f),
                       fmaxf(fmaf(v.y, al, be), 0.f),
                       fmaxf(fmaf(v.z, al, be), 0.f),
                       fmaxf(fmaf(v.w, al, be), 0.f));
}

// warp xor-reduce of a float4 (result in all lanes)
__device__ __forceinline__ float4 wred4(float4 s) {
    #pragma unroll
    for (int d = 16; d > 0; d >>= 1) {
        s.x += __shfl_xor_sync(0xffffffffu, s.x, d);
        s.y += __shfl_xor_sync(0xffffffffu, s.y, d);
        s.z += __shfl_xor_sync(0xffffffffu, s.z, d);
        s.w += __shfl_xor_sync(0xffffffffu, s.w, d);
    }
    return s;
}

#define ZERO4 make_float4(0.f, 0.f, 0.f, 0.f)

__global__ void __launch_bounds__(128) taunet_main(const float* __restrict__ x,
                                                   float* __restrict__ out, int nB)
{
    __shared__ __align__(16) float s_small[SMALL_N];
    __shared__ __align__(16) float s_ws[4][WS_N];

    for (int i = threadIdx.x; i < SMALL_N; i += 128) s_small[i] = g_small[i];
    __syncthreads();
    // fold weight sums into beta: be2 = be - al*Wsum
    for (int i = threadIdx.x; i < NSUM; i += 128) {
        float wsv = g_wsum[i];
        if (i < 5)        s_small[B1OFF + i]          -= s_small[A1OFF + i]          * wsv;
        else if (i < 15)  s_small[B2OFF + (i - 5)]    -= s_small[A2OFF + (i - 5)]    * wsv;
        else if (i < 25)  s_small[BR1OFF + (i - 15)]  -= s_small[AR1OFF + (i - 15)]  * wsv;
        else if (i < 35)  s_small[BR2OFF + (i - 25)]  -= s_small[AR2OFF + (i - 25)]  * wsv;
        else if (i < 175) s_small[BOAOFF + (i - 35)]  -= s_small[AOAOFF + (i - 35)]  * wsv;
        else              s_small[BOBOFF + (i - 175)] -= s_small[AOBOFF + (i - 175)] * wsv;
    }
    __syncthreads();

    const int warp = threadIdx.x >> 5, lane = threadIdx.x & 31;
    float* ws = s_ws[warp];
    float4* X4  = (float4*)(ws + XOFF);
    float4* H14 = (float4*)(ws + H1OFF);
    float4* H24 = (float4*)(ws + H2OFF);
    float4* T4  = (float4*)(ws + XOFF);
    float4* F4  = (float4*)(ws + FOFF);
    float4* A4  = (float4*)(ws + AOFF);
    float4* B4  = (float4*)(ws + BOFF);
    float4* SX4 = (float4*)(ws + H2OFF);        // pre1 window sums (49)
    float4* SW4 = (float4*)(ws + XOFF) + 160;   // pre2 window sums (14)
    float4* RSa = (float4*)(ws + XOFF) + 180;   // r1 input sums (14)
    float4* RSb = (float4*)(ws + XOFF) + 200;   // r2 input sums (14)

    // ---- per-lane o-layer slot precompute ----
    const int j2 = lane + 64, j3 = lane + 96;
    const int j4 = (lane + 128 < 140) ? lane + 128 : 139;
    const int oa2 = (j2 < 70) ? j2 : (2450 + (j2 - 70));
    const int oa3 = 2450 + (j3 - 70);
    const int oa4 = 2450 + (j4 - 70);
    const int d2 = (j2 < 70) ? j2 : (72 + (j2 - 70));
    const int d3 = 72 + (j3 - 70);
    const int d4 = 72 + (j4 - 70);
    const int jb1 = (lane + 32 < 60) ? lane + 32 : 59;
    const int obb0 = lane / 30, obc0 = lane - 30 * obb0;
    const int ob0 = obb0 * 540 + obc0;
    const int ob1 = 540 + (jb1 - 30);
    const int rp = lane >> 1, rg = lane & 1;

    const int nQ = (nB + 3) >> 2;
    const int gw = blockIdx.x * 4 + warp;
    const int stride = gridDim.x * 4;

    for (int q = gw; q < nQ; q += stride) {
        const int e0 = 4 * q;
        const int e1 = (e0 + 1 < nB) ? e0 + 1 : nB - 1;
        const int e2 = (e0 + 2 < nB) ? e0 + 2 : nB - 1;
        const int e3 = (e0 + 3 < nB) ? e0 + 3 : nB - 1;

        // ---- stage 4 input rows, transposed into float4-per-position ----
        {
            const float4* r0 = (const float4*)(x + (size_t)e0 * 256);
            const float4* r1 = (const float4*)(x + (size_t)e1 * 256);
            const float4* r2 = (const float4*)(x + (size_t)e2 * 256);
            const float4* r3 = (const float4*)(x + (size_t)e3 * 256);
            #pragma unroll
            for (int i = 0; i < 2; i++) {
                int m = lane + 32 * i;
                float4 a = __ldg(r0 + m);
                float4 b = __ldg(r1 + m);
                float4 c = __ldg(r2 + m);
                float4 d = __ldg(r3 + m);
                X4[4 * m + 0] = make_float4(a.x, b.x, c.x, d.x);
                X4[4 * m + 1] = make_float4(a.y, b.y, c.y, d.y);
                X4[4 * m + 2] = make_float4(a.z, b.z, c.z, d.z);
                X4[4 * m + 3] = make_float4(a.w, b.w, c.w, d.w);
            }
        }
        __syncwarp();

        // ---- pre1 window sums SX[p] = sum_{k<13} X4[5p+k]  (into H2 region) --
        #pragma unroll
        for (int r = 0; r < 2; r++) {
            int p = lane + 32 * r;
            if (p < 49) {
                const float4* xp = X4 + 5 * p;
                float4 s = xp[0];
                #pragma unroll
                for (int k = 1; k < 13; k++) s = add4(s, xp[k]);
                SX4[p] = s;
            }
        }
        __syncwarp();

        // ---- pre1: 125 dual-position tasks, min-accumulation ----
        #pragma unroll 1
        for (int r = 0; r < 4; r++) {
            int idx = lane + 32 * r;
            if (idx < 125) {
                int pd = idx / 5, c = idx - 5 * pd;
                int p0 = 2 * pd;
                bool dual = (pd < 24);
                float w[16];
                const float* wb = s_small + W1OFF + c * 16;
                ld4(w, wb); ld4(w + 4, wb + 4); ld4(w + 8, wb + 8); ld4(w + 12, wb + 12);
                const float4* xp = X4 + 5 * p0;
                float4 A0 = ZERO4, B0 = ZERO4, A1 = ZERO4, B1 = ZERO4;
                #pragma unroll
                for (int k = 0; k < 13; k++) {
                    float4 a = xp[k];
                    if (k & 1) accm4(B0, a, w[k]); else accm4(A0, a, w[k]);
                    if (k >= 5) {
                        if ((k - 5) & 1) accm4(B1, a, w[k - 5]); else accm4(A1, a, w[k - 5]);
                    }
                }
                if (dual) {
                    #pragma unroll
                    for (int k = 13; k < 18; k++) {
                        float4 a = xp[k];
                        if ((k - 5) & 1) accm4(B1, a, w[k - 5]); else accm4(A1, a, w[k - 5]);
                    }
                }
                float al = s_small[A1OFF + c], be = s_small[B1OFF + c];
                H14[c * 49 + p0] = bnrelu4p(v2sa(add4(A0, B0), SX4[p0]), al, be);
                if (dual)
                    H14[c * 49 + p0 + 1] = bnrelu4p(v2sa(add4(A1, B1), SX4[p0 + 1]), al, be);
            }
        }
        __syncwarp();

        // ---- pre2 window sums SW[p] = sum_{ci<5,k<9} H1[ci][3p+k] (X region) --
        if (lane < 14) {
            const float4* hp = H14 + 3 * lane;
            float4 s = ZERO4;
            #pragma unroll
            for (int ci = 0; ci < 5; ci++) {
                const float4* hc = hp + ci * 49;
                #pragma unroll
                for (int k = 0; k < 9; k++) s = add4(s, hc[k]);
            }
            SW4[lane] = s;
        }
        __syncwarp();

        // ---- pre2: 70 dual-position tasks, min-accumulation ----
        #pragma unroll 1
        for (int r = 0; r < 3; r++) {
            int idx = lane + 32 * r;
            if (idx < 70) {
                int pd = idx / 10, c = idx - 10 * pd;
                int p0 = 2 * pd;
                const float4* hp = H14 + 3 * p0;
                float4 A0 = ZERO4, B0 = ZERO4, A1 = ZERO4, B1 = ZERO4;
                #pragma unroll
                for (int ci = 0; ci < 5; ci++) {
                    float w[12];
                    const float* wb = s_small + W2OFF + (c * 5 + ci) * 12;
                    ld4(w, wb); ld4(w + 4, wb + 4); ld4(w + 8, wb + 8);
                    const float4* hc = hp + ci * 49;
                    #pragma unroll
                    for (int k = 0; k < 12; k++) {
                        float4 a = hc[k];
                        if (k < 9) {
                            if (k & 1) accm4(B0, a, w[k]); else accm4(A0, a, w[k]);
                        }
                        if (k >= 3) {
                            if ((k - 3) & 1) accm4(B1, a, w[k - 3]); else accm4(A1, a, w[k - 3]);
                        }
                    }
                }
                float al = s_small[A2OFF + c], be = s_small[B2OFF + c];
                H24[c * 14 + p0]     = bnrelu4p(v2sa(add4(A0, B0), SW4[p0]),     al, be);
                H24[c * 14 + p0 + 1] = bnrelu4p(v2sa(add4(A1, B1), SW4[p0 + 1]), al, be);
            }
        }
        __syncwarp();

        // ---- r1 input sums RSa[p] = sum_ci H2[ci][p] ----
        if (lane < 14) {
            float4 s = H24[lane];
            #pragma unroll
            for (int ci = 1; ci < 10; ci++) s = add4(s, H24[ci * 14 + lane]);
            RSa[lane] = s;
        }
        __syncwarp();

        // ---- r1: position-major, lanes 0..27 = (p, g); min-accumulation ----
        if (lane < 28) {
            float4 acc[5];
            #pragma unroll
            for (int j = 0; j < 5; j++) acc[j] = ZERO4;
            const float* wt = s_small + R1TOFF + 8 * rg;
            #pragma unroll
            for (int ci = 0; ci < 10; ci++) {
                float4 a = H24[ci * 14 + rp];
                float w8[8];
                ld4(w8, wt + ci * 16); ld4(w8 + 4, wt + ci * 16 + 4);
                #pragma unroll
                for (int j = 0; j < 5; j++) accm4(acc[j], a, w8[j]);
            }
            float4 rs = RSa[rp];
            #pragma unroll
            for (int j = 0; j < 5; j++) {
                int c = 5 * rg + j;
                T4[c * 14 + rp] = bnrelu4p(v2sa(acc[j], rs),
                                           s_small[AR1OFF + c], s_small[BR1OFF + c]);
            }
        }
        __syncwarp();

        // ---- r2 input sums RSb[p] = sum_ci T[ci][p] ----
        if (lane < 14) {
            float4 s = T4[lane];
            #pragma unroll
            for (int ci = 1; ci < 10; ci++) s = add4(s, T4[ci * 14 + lane]);
            RSb[lane] = s;
        }
        __syncwarp();

        // ---- r2 + residual: min-accumulation, F over dead H1 ----
        if (lane < 28) {
            float4 acc[5];
            #pragma unroll
            for (int j = 0; j < 5; j++) acc[j] = ZERO4;
            const float* wt = s_small + R2TOFF + 8 * rg;
            #pragma unroll
            for (int ci = 0; ci < 10; ci++) {
                float4 a = T4[ci * 14 + rp];
                float w8[8];
                ld4(w8, wt + ci * 16); ld4(w8 + 4, wt + ci * 16 + 4);
                #pragma unroll
                for (int j = 0; j < 5; j++) accm4(acc[j], a, w8[j]);
            }
            float4 rs = RSb[rp];
            #pragma unroll
            for (int j = 0; j < 5; j++) {
                int c = 5 * rg + j;
                float al = s_small[AR2OFF + c], be = s_small[BR2OFF + c];
                float4 h2v = H24[c * 14 + rp];
                float4 v = v2sa(acc[j], rs);
                F4[c * 14 + rp] = make_float4(
                    fmaxf(fmaf(v.x, al, be) + h2v.x, 0.f),
                    fmaxf(fmaf(v.y, al, be) + h2v.y, 0.f),
                    fmaxf(fmaf(v.z, al, be) + h2v.z, 0.f),
                    fmaxf(fmaf(v.w, al, be) + h2v.w, 0.f));
            }
        }
        if (lane < 4) F4[140 + lane] = ZERO4;
        __syncwarp();

        // ---- FSUM = sum_i F4[i] (pads zero), broadcast via xor-reduce ----
        float4 fs;
        {
            fs = add4(add4(F4[lane], F4[lane + 32]), add4(F4[lane + 64], F4[lane + 96]));
            if (lane + 128 < 144) fs = add4(fs, F4[lane + 128]);
            fs = wred4(fs);
        }

        // ---- oa: 5 channel slots x 4 packed elements, min-accumulation ----
        {
            float4 acc[5];
            #pragma unroll
            for (int s = 0; s < 5; s++) acc[s] = ZERO4;

            const int slots[5] = {lane, lane + 32, oa2, oa3, oa4};
            const float4* QA = (const float4*)g_qoa;

            #pragma unroll 5
            for (int i4 = 0; i4 < 35; i4++) {
                float4 u0 = F4[4 * i4 + 0];
                float4 u1 = F4[4 * i4 + 1];
                float4 u2 = F4[4 * i4 + 2];
                float4 u3 = F4[4 * i4 + 3];
                const float4* qrow = QA + i4 * 70;
                #pragma unroll
                for (int s = 0; s < 5; s++) {
                    float4 w = __ldg(qrow + slots[s]);
                    accm4(acc[s], u0, w.x);
                    accm4(acc[s], u1, w.y);
                    accm4(acc[s], u2, w.z);
                    accm4(acc[s], u3, w.w);
                }
            }
            __syncwarp();   // F reads done before A overwrite of X region

            const int js[5] = {lane, lane + 32, j2, j3, j4};
            const int ds[5] = {lane, lane + 32, d2, d3, d4};
            #pragma unroll
            for (int s = 0; s < 5; s++) {
                A4[ds[s]] = bnrelu4p(v2sa(acc[s], fs),
                                     s_small[AOAOFF + js[s]], s_small[BOAOFF + js[s]]);
            }
            if (lane < 2) {
                A4[70 + lane]  = ZERO4;
                A4[142 + lane] = ZERO4;
            }
        }
        __syncwarp();

        // ---- branch sums over A (72 float4 each, pads zero) ----
        float4 as0, as1;
        {
            float4 s0 = add4(A4[lane], A4[lane + 32]);
            if (lane + 64 < 72) s0 = add4(s0, A4[lane + 64]);
            float4 s1 = add4(A4[72 + lane], A4[72 + lane + 32]);
            if (lane + 64 < 72) s1 = add4(s1, A4[72 + lane + 64]);
            s0 = wred4(s0);
            s1 = wred4(s1);
            as0 = (obb0 == 0) ? s0 : s1;
            as1 = s1;
        }

        // ---- ob: 2 channel slots x 4 packed elements, min-accumulation ----
        {
            float4 b0 = ZERO4;
            float4 b1 = ZERO4;
            const float4* QB = (const float4*)g_qob;
            const float4* a0p = A4 + obb0 * 72;
            const float4* a1p = A4 + 72;

            #pragma unroll 6
            for (int i4 = 0; i4 < 18; i4++) {
                float4 w0 = __ldg(QB + i4 * 30 + ob0);
                accm4(b0, a0p[4 * i4 + 0], w0.x);
                accm4(b0, a0p[4 * i4 + 1], w0.y);
                accm4(b0, a0p[4 * i4 + 2], w0.z);
                accm4(b0, a0p[4 * i4 + 3], w0.w);
                float4 w1 = __ldg(QB + i4 * 30 + ob1);
                accm4(b1, a1p[4 * i4 + 0], w1.x);
                accm4(b1, a1p[4 * i4 + 1], w1.y);
                accm4(b1, a1p[4 * i4 + 2], w1.z);
                accm4(b1, a1p[4 * i4 + 3], w1.w);
            }
            __syncwarp();   // A reads done before B overwrite of H2 region

            B4[obb0 * 32 + obc0] = bnrelu4p(v2sa(b0, as0),
                                            s_small[AOBOFF + lane], s_small[BOBOFF + lane]);
            B4[32 + (jb1 - 30)]  = bnrelu4p(v2sa(b1, as1),
                                            s_small[AOBOFF + jb1], s_small[BOBOFF + jb1]);
            if (lane < 2) {
                B4[30 + lane] = ZERO4;
                B4[62 + lane] = ZERO4;
            }
        }
        __syncwarp();

        // ---- oc: 8 reductions (4 elems x 2 branches), classic |diff| ----
        {
            float w0 = s_small[QOCOFF + lane], w1 = s_small[QOCOFF + 32 + lane];
            float4 p0 = B4[lane];
            float4 p1 = B4[32 + lane];
            float vA0 = fabsf(p0.x - w0), vA1 = fabsf(p0.y - w0);
            float vA2 = fabsf(p0.z - w0), vA3 = fabsf(p0.w - w0);
            float vI0 = fabsf(p1.x - w1), vI1 = fabsf(p1.y - w1);
            float vI2 = fabsf(p1.z - w1), vI3 = fabsf(p1.w - w1);
            #pragma unroll
            for (int s = 16; s > 0; s >>= 1) {
                vA0 += __shfl_xor_sync(0xffffffffu, vA0, s);
                vA1 += __shfl_xor_sync(0xffffffffu, vA1, s);
                vA2 += __shfl_xor_sync(0xffffffffu, vA2, s);
                vA3 += __shfl_xor_sync(0xffffffffu, vA3, s);
                vI0 += __shfl_xor_sync(0xffffffffu, vI0, s);
                vI1 += __shfl_xor_sync(0xffffffffu, vI1, s);
                vI2 += __shfl_xor_sync(0xffffffffu, vI2, s);
                vI3 += __shfl_xor_sync(0xffffffffu, vI3, s);
            }
            if (lane == 0) {
                float aA = s_small[AOCOFF],     bA = s_small[BOCOFF];
                float aI = s_small[AOCOFF + 1], bI = s_small[BOCOFF + 1];
                float vA[4] = {vA0, vA1, vA2, vA3};
                float vI[4] = {vI0, vI1, vI2, vI3};
                #pragma unroll
                for (int i = 0; i < 4; i++) {
                    if (e0 + i < nB) {
                        out[e0 + i]      = fmaxf(fmaf(-vA[i], aA, bA), 0.f);
                        out[nB + e0 + i] = fmaxf(fmaf(-vI[i], aI, bI), 0.f);
                    }
                }
            }
        }
        __syncwarp();   // B reads done before next iteration overwrites
    }
}

// ---------------------------------------------------------------------------
extern "C" void kernel_launch(void* const* d_in, const int* in_sizes, int n_in,
                              void* d_out, int out_size)
{
    const float* x     = (const float*)d_in[0];
    const float* w1    = (const float*)d_in[1];
    const float* bn1   = (const float*)d_in[2];
    const float* w2    = (const float*)d_in[3];
    const float* bn2   = (const float*)d_in[4];
    const float* wr1   = (const float*)d_in[5];
    const float* bnr1  = (const float*)d_in[6];
    const float* wr2   = (const float*)d_in[7];
    const float* bnr2  = (const float*)d_in[8];
    const float* wo1a  = (const float*)d_in[9];
    const float* bno1a = (const float*)d_in[10];
    const float* wo1b  = (const float*)d_in[11];
    const float* bno1b = (const float*)d_in[12];
    const float* wo1c  = (const float*)d_in[13];
    const float* bno1c = (const float*)d_in[14];
    const float* wo2a  = (const float*)d_in[15];
    const float* bno2a = (const float*)d_in[16];
    const float* wo2b  = (const float*)d_in[17];
    const float* bno2b = (const float*)d_in[18];
    const float* wo2c  = (const float*)d_in[19];
    const float* bno2c = (const float*)d_in[20];

    const int nB = in_sizes[0] / 256;

    setup_kernel<<<11, 256>>>(w1, w2, wr1, wr2, wo1a, wo1b, wo1c, wo2a, wo2b, wo2c,
                              bn1, bn2, bnr1, bnr2, bno1a, bno1b, bno1c,
                              bno2a, bno2b, bno2c);
    taunet_main<<<512, 128>>>(x, (float*)d_out, nB);
}

// round 16
// speedup vs baseline: 1.0348x; 1.0348x over previous
#include <cuda_runtime.h>

// ============================================================================
// AdderNet TauNet R16: R14 + min-identity ONLY in oa/ob (the big layers):
// sum|a-w| = sumA + sumW - 2*sum min(a,w); sumW folded into beta,
// sumA shared per quad via one warp reduction. pre/r stages classic |diff|.
// ============================================================================

#define EPSV 1e-5f

// ---- s_small layout (floats), compact ----
#define W1OFF   0      // 5 x 16
#define W2OFF   80     // 50 x 12
#define R1TOFF  680    // 10ci x 16
#define R2TOFF  840    // 10ci x 16
#define A1OFF   1000
#define B1OFF   1005
#define A2OFF   1010
#define B2OFF   1020
#define AR1OFF  1030
#define BR1OFF  1040
#define AR2OFF  1050
#define BR2OFF  1060
#define AOAOFF  1070   // 140
#define BOAOFF  1210   // 140
#define AOBOFF  1350   // 60
#define BOBOFF  1410   // 60
#define AOCOFF  1470   // 2
#define BOCOFF  1472   // 2
#define QOCOFF  1474   // 64
#define SMALL_N 1540

__device__ float g_small[1544];
__device__ float g_wsum[200];              // oa sums [0:140), ob sums [140:200)
__device__ float g_qoa[2 * 35 * 70 * 4];   // [branch][i/4][c][4]
__device__ float g_qob[2 * 18 * 30 * 4];

__device__ __forceinline__ float quantv(float w, float s) {
    float t = fminf(fmaxf(w / s, -127.f), 127.f);
    return rintf(t) * s;
}

__device__ __forceinline__ void fill_bn(const float* bn, int c, float* A, float* Bt) {
    for (int i = threadIdx.x; i < c; i += blockDim.x) {
        float g = bn[i], b = bn[c + i], m = bn[2 * c + i], v = bn[3 * c + i];
        float al = g * rsqrtf(v + EPSV);
        A[i] = al;
        Bt[i] = b - m * al;
    }
}

// ---------------------------------------------------------------------------
__global__ void setup_kernel(
    const float* __restrict__ w1,   const float* __restrict__ w2,
    const float* __restrict__ wr1,  const float* __restrict__ wr2,
    const float* __restrict__ wo1a, const float* __restrict__ wo1b, const float* __restrict__ wo1c,
    const float* __restrict__ wo2a, const float* __restrict__ wo2b, const float* __restrict__ wo2c,
    const float* __restrict__ bn1,  const float* __restrict__ bn2,
    const float* __restrict__ bnr1, const float* __restrict__ bnr2,
    const float* __restrict__ bno1a, const float* __restrict__ bno1b, const float* __restrict__ bno1c,
    const float* __restrict__ bno2a, const float* __restrict__ bno2b, const float* __restrict__ bno2c)
{
    const int blk = blockIdx.x, tid = threadIdx.x;
    if (blk < 10) {
        const float* w; int n;
        switch (blk) {
            case 0: w = w1;   n = 65;   break;
            case 1: w = w2;   n = 450;  break;
            case 2: w = wr1;  n = 100;  break;
            case 3: w = wr2;  n = 100;  break;
            case 4: w = wo1a; n = 9800; break;
            case 5: w = wo2a; n = 9800; break;
            case 6: w = wo1b; n = 2100; break;
            case 7: w = wo2b; n = 2100; break;
            case 8: w = wo1c; n = 30;   break;
            default: w = wo2c; n = 30;  break;
        }
        __shared__ float red[256];
        float m = 0.f;
        for (int i = tid; i < n; i += 256) m = fmaxf(m, fabsf(w[i]));
        red[tid] = m;
        __syncthreads();
        for (int s = 128; s > 0; s >>= 1) {
            if (tid < s) red[tid] = fmaxf(red[tid], red[tid + s]);
            __syncthreads();
        }
        const float s = red[0] / 127.f;

        if (blk == 0) {
            for (int j = tid; j < 80; j += 256) {
                int c = j >> 4, k = j & 15;
                g_small[W1OFF + j] = (k < 13) ? quantv(w[c * 13 + k], s) : 0.f;
            }
        } else if (blk == 1) {
            for (int j = tid; j < 600; j += 256) {
                int row = j / 12, k = j - row * 12;
                g_small[W2OFF + j] = (k < 9) ? quantv(w[row * 9 + k], s) : 0.f;
            }
        } else if (blk == 2 || blk == 3) {
            float* dst = g_small + (blk == 2 ? R1TOFF : R2TOFF);
            for (int j = tid; j < 160; j += 256) {
                int ci = j >> 4, rem = j & 15;
                int g = rem >> 3, k = rem & 7;
                int c = 5 * g + k;
                dst[j] = (k < 5) ? quantv(w[c * 10 + ci], s) : 0.f;
            }
        } else if (blk == 4 || blk == 5) {
            float* dst = g_qoa + (blk - 4) * 9800;
            for (int j = tid; j < 9800; j += 256) {
                int i4 = j / 280, rem = j - i4 * 280;
                int c = rem >> 2, t = rem & 3;
                dst[j] = quantv(w[c * 140 + i4 * 4 + t], s);
            }
            if (tid < 70) {
                float sm = 0.f;
                for (int i = 0; i < 140; i++) sm += quantv(w[tid * 140 + i], s);
                g_wsum[(blk - 4) * 70 + tid] = sm;
            }
        } else if (blk == 6 || blk == 7) {
            float* dst = g_qob + (blk - 6) * 2160;
            for (int j = tid; j < 2160; j += 256) {
                int i4 = j / 120, rem = j - i4 * 120;
                int c = rem >> 2, t = rem & 3;
                int i = i4 * 4 + t;
                dst[j] = (i < 70) ? quantv(w[c * 70 + i], s) : 0.f;
            }
            if (tid < 30) {
                float sm = 0.f;
                for (int i = 0; i < 70; i++) sm += quantv(w[tid * 70 + i], s);
                g_wsum[140 + (blk - 6) * 30 + tid] = sm;
            }
        } else {
            float* dst = g_small + QOCOFF + (blk - 8) * 32;
            if (tid < 32) dst[tid] = (tid < 30) ? quantv(w[tid], s) : 0.f;
        }
    } else {
        fill_bn(bn1, 5,  g_small + A1OFF,  g_small + B1OFF);
        fill_bn(bn2, 10, g_small + A2OFF,  g_small + B2OFF);
        fill_bn(bnr1, 10, g_small + AR1OFF, g_small + BR1OFF);
        fill_bn(bnr2, 10, g_small + AR2OFF, g_small + BR2OFF);
        fill_bn(bno1a, 70, g_small + AOAOFF,      g_small + BOAOFF);
        fill_bn(bno2a, 70, g_small + AOAOFF + 70, g_small + BOAOFF + 70);
        fill_bn(bno1b, 30, g_small + AOBOFF,      g_small + BOBOFF);
        fill_bn(bno2b, 30, g_small + AOBOFF + 30, g_small + BOBOFF + 30);
        fill_bn(bno1c, 1, g_small + AOCOFF,     g_small + BOCOFF);
        fill_bn(bno2c, 1, g_small + AOCOFF + 1, g_small + BOCOFF + 1);
    }
}

// ---------------------------------------------------------------------------
// Per-warp workspace (floats), same aliasing map as R14.
#define XOFF  0
#define H1OFF 1024
#define H2OFF 2004
#define FOFF  1024
#define AOFF  0
#define BOFF  2004
#define WS_N  2580

__device__ __forceinline__ void ld4(float* d, const float* s) {
    float4 v = *(const float4*)s;
    d[0] = v.x; d[1] = v.y; d[2] = v.z; d[3] = v.w;
}

// d = u - w as FFMA-imm
__device__ __forceinline__ float fdiff(float u, float w) {
    float d;
    asm("fma.rn.f32 %0, %1, 0fBF800000, %2;" : "=f"(d) : "f"(w), "f"(u));
    return d;
}

__device__ __forceinline__ void acc4(float4& a, float4 u, float w) {
    a.x += fabsf(fdiff(u.x, w));
    a.y += fabsf(fdiff(u.y, w));
    a.z += fabsf(fdiff(u.z, w));
    a.w += fabsf(fdiff(u.w, w));
}

// acc += min(u, w): FMNMX (alu) + FADD (fma)
__device__ __forceinline__ void accm4(float4& a, float4 u, float w) {
    a.x += fminf(u.x, w);
    a.y += fminf(u.y, w);
    a.z += fminf(u.z, w);
    a.w += fminf(u.w, w);
}

__device__ __forceinline__ float4 add4(float4 a, float4 b) {
    return make_float4(a.x + b.x, a.y + b.y, a.z + b.z, a.w + b.w);
}

// v = 2*S - A
__device__ __forceinline__ float4 v2sa(float4 S, float4 A) {
    return make_float4(fmaf(2.f, S.x, -A.x), fmaf(2.f, S.y, -A.y),
                       fmaf(2.f, S.z, -A.z), fmaf(2.f, S.w, -A.w));
}

__device__ __forceinline__ float4 bnrelu4(float4 a, float al, float be) {
    return make_float4(fmaxf(fmaf(-a.x, al, be), 0.f),
                       fmaxf(fmaf(-a.y, al, be), 0.f),
                       fmaxf(fmaf(-a.z, al, be), 0.f),
                       fmaxf(fmaf(-a.w, al, be), 0.f));
}

// relu(v*al + be2)  (positive-slope form for min-identity layers)
__device__ __forceinline__ float4 bnrelu4p(float4 v, float al, float be) {
    return make_float4(fmaxf(fmaf(v.x, al, be), 0.f),
                       fmaxf(fmaf(v.y, al, be), 0.f),
                       fmaxf(fmaf(v.z, al, be), 0.f),
                       fmaxf(fmaf(v.w, al, be), 0.f));
}

__device__ __forceinline__ float4 wred4(float4 s) {
    #pragma unroll
    for (int d = 16; d > 0; d >>= 1) {
        s.x += __shfl_xor_sync(0xffffffffu, s.x, d);
        s.y += __shfl_xor_sync(0xffffffffu, s.y, d);
        s.z += __shfl_xor_sync(0xffffffffu, s.z, d);
        s.w += __shfl_xor_sync(0xffffffffu, s.w, d);
    }
    return s;
}

#define ZERO4 make_float4(0.f, 0.f, 0.f, 0.f)

__global__ void __launch_bounds__(128) taunet_main(const float* __restrict__ x,
                                                   float* __restrict__ out, int nB)
{
    __shared__ __align__(16) float s_small[SMALL_N];
    __shared__ __align__(16) float s_ws[4][WS_N];

    for (int i = threadIdx.x; i < SMALL_N; i += 128) s_small[i] = g_small[i];
    __syncthreads();
    // fold oa/ob weight sums into beta: be2 = be - al*Wsum
    if (threadIdx.x < 128) {
        for (int i = threadIdx.x; i < 200; i += 128) {
            float wsv = g_wsum[i];
            if (i < 140) s_small[BOAOFF + i]         -= s_small[AOAOFF + i]         * wsv;
            else         s_small[BOBOFF + (i - 140)] -= s_small[AOBOFF + (i - 140)] * wsv;
        }
    }
    __syncthreads();

    const int warp = threadIdx.x >> 5, lane = threadIdx.x & 31;
    float* ws = s_ws[warp];
    float4* X4  = (float4*)(ws + XOFF);
    float4* H14 = (float4*)(ws + H1OFF);
    float4* H24 = (float4*)(ws + H2OFF);
    float4* T4  = (float4*)(ws + XOFF);
    float4* F4  = (float4*)(ws + FOFF);
    float4* A4  = (float4*)(ws + AOFF);
    float4* B4  = (float4*)(ws + BOFF);

    // ---- per-lane o-layer slot precompute ----
    const int j2 = lane + 64, j3 = lane + 96;
    const int j4 = (lane + 128 < 140) ? lane + 128 : 139;
    const int oa2 = (j2 < 70) ? j2 : (2450 + (j2 - 70));
    const int oa3 = 2450 + (j3 - 70);
    const int oa4 = 2450 + (j4 - 70);
    const int d2 = (j2 < 70) ? j2 : (72 + (j2 - 70));
    const int d3 = 72 + (j3 - 70);
    const int d4 = 72 + (j4 - 70);
    const int jb1 = (lane + 32 < 60) ? lane + 32 : 59;
    const int obb0 = lane / 30, obc0 = lane - 30 * obb0;
    const int ob0 = obb0 * 540 + obc0;
    const int ob1 = 540 + (jb1 - 30);
    const int rp = lane >> 1, rg = lane & 1;

    const int nQ = (nB + 3) >> 2;
    const int gw = blockIdx.x * 4 + warp;
    const int stride = gridDim.x * 4;

    for (int q = gw; q < nQ; q += stride) {
        const int e0 = 4 * q;
        const int e1 = (e0 + 1 < nB) ? e0 + 1 : nB - 1;
        const int e2 = (e0 + 2 < nB) ? e0 + 2 : nB - 1;
        const int e3 = (e0 + 3 < nB) ? e0 + 3 : nB - 1;

        // ---- stage 4 input rows, transposed into float4-per-position ----
        {
            const float4* r0 = (const float4*)(x + (size_t)e0 * 256);
            const float4* r1 = (const float4*)(x + (size_t)e1 * 256);
            const float4* r2 = (const float4*)(x + (size_t)e2 * 256);
            const float4* r3 = (const float4*)(x + (size_t)e3 * 256);
            #pragma unroll
            for (int i = 0; i < 2; i++) {
                int m = lane + 32 * i;
                float4 a = __ldg(r0 + m);
                float4 b = __ldg(r1 + m);
                float4 c = __ldg(r2 + m);
                float4 d = __ldg(r3 + m);
                X4[4 * m + 0] = make_float4(a.x, b.x, c.x, d.x);
                X4[4 * m + 1] = make_float4(a.y, b.y, c.y, d.y);
                X4[4 * m + 2] = make_float4(a.z, b.z, c.z, d.z);
                X4[4 * m + 3] = make_float4(a.w, b.w, c.w, d.w);
            }
        }
        __syncwarp();

        // ---- pre1: 125 dual-position tasks, channel-fastest, classic |diff| --
        #pragma unroll 1
        for (int r = 0; r < 4; r++) {
            int idx = lane + 32 * r;
            if (idx < 125) {
                int pd = idx / 5, c = idx - 5 * pd;
                int p0 = 2 * pd;
                bool dual = (pd < 24);
                float w[16];
                const float* wb = s_small + W1OFF + c * 16;
                ld4(w, wb); ld4(w + 4, wb + 4); ld4(w + 8, wb + 8); ld4(w + 12, wb + 12);
                const float4* xp = X4 + 5 * p0;
                float4 A0 = ZERO4, B0 = ZERO4, A1 = ZERO4, B1 = ZERO4;
                #pragma unroll
                for (int k = 0; k < 13; k++) {
                    float4 a = xp[k];
                    if (k & 1) acc4(B0, a, w[k]); else acc4(A0, a, w[k]);
                    if (k >= 5) {
                        if ((k - 5) & 1) acc4(B1, a, w[k - 5]); else acc4(A1, a, w[k - 5]);
                    }
                }
                if (dual) {
                    #pragma unroll
                    for (int k = 13; k < 18; k++) {
                        float4 a = xp[k];
                        if ((k - 5) & 1) acc4(B1, a, w[k - 5]); else acc4(A1, a, w[k - 5]);
                    }
                }
                float al = s_small[A1OFF + c], be = s_small[B1OFF + c];
                H14[c * 49 + p0] = bnrelu4(add4(A0, B0), al, be);
                if (dual)
                    H14[c * 49 + p0 + 1] = bnrelu4(add4(A1, B1), al, be);
            }
        }
        __syncwarp();

        // ---- pre2: 70 dual-position tasks, channel-fastest, classic |diff| --
        #pragma unroll 1
        for (int r = 0; r < 3; r++) {
            int idx = lane + 32 * r;
            if (idx < 70) {
                int pd = idx / 10, c = idx - 10 * pd;
                int p0 = 2 * pd;
                const float4* hp = H14 + 3 * p0;
                float4 A0 = ZERO4, B0 = ZERO4, A1 = ZERO4, B1 = ZERO4;
                #pragma unroll
                for (int ci = 0; ci < 5; ci++) {
                    float w[12];
                    const float* wb = s_small + W2OFF + (c * 5 + ci) * 12;
                    ld4(w, wb); ld4(w + 4, wb + 4); ld4(w + 8, wb + 8);
                    const float4* hc = hp + ci * 49;
                    #pragma unroll
                    for (int k = 0; k < 12; k++) {
                        float4 a = hc[k];
                        if (k < 9) {
                            if (k & 1) acc4(B0, a, w[k]); else acc4(A0, a, w[k]);
                        }
                        if (k >= 3) {
                            if ((k - 3) & 1) acc4(B1, a, w[k - 3]); else acc4(A1, a, w[k - 3]);
                        }
                    }
                }
                float al = s_small[A2OFF + c], be = s_small[B2OFF + c];
                H24[c * 14 + p0]     = bnrelu4(add4(A0, B0), al, be);
                H24[c * 14 + p0 + 1] = bnrelu4(add4(A1, B1), al, be);
            }
        }
        __syncwarp();

        // ---- r1: position-major, classic |diff| ----
        if (lane < 28) {
            float4 acc[5];
            #pragma unroll
            for (int j = 0; j < 5; j++) acc[j] = ZERO4;
            const float* wt = s_small + R1TOFF + 8 * rg;
            #pragma unroll
            for (int ci = 0; ci < 10; ci++) {
                float4 a = H24[ci * 14 + rp];
                float w8[8];
                ld4(w8, wt + ci * 16); ld4(w8 + 4, wt + ci * 16 + 4);
                #pragma unroll
                for (int j = 0; j < 5; j++) acc4(acc[j], a, w8[j]);
            }
            #pragma unroll
            for (int j = 0; j < 5; j++) {
                int c = 5 * rg + j;
                T4[c * 14 + rp] = bnrelu4(acc[j], s_small[AR1OFF + c], s_small[BR1OFF + c]);
            }
        }
        __syncwarp();

        // ---- r2 + residual, classic |diff| ----
        if (lane < 28) {
            float4 acc[5];
            #pragma unroll
            for (int j = 0; j < 5; j++) acc[j] = ZERO4;
            const float* wt = s_small + R2TOFF + 8 * rg;
            #pragma unroll
            for (int ci = 0; ci < 10; ci++) {
                float4 a = T4[ci * 14 + rp];
                float w8[8];
                ld4(w8, wt + ci * 16); ld4(w8 + 4, wt + ci * 16 + 4);
                #pragma unroll
                for (int j = 0; j < 5; j++) acc4(acc[j], a, w8[j]);
            }
            #pragma unroll
            for (int j = 0; j < 5; j++) {
                int c = 5 * rg + j;
                float al = s_small[AR2OFF + c], be = s_small[BR2OFF + c];
                float4 h2v = H24[c * 14 + rp];
                float4 a = acc[j];
                F4[c * 14 + rp] = make_float4(
                    fmaxf(fmaf(-a.x, al, be) + h2v.x, 0.f),
                    fmaxf(fmaf(-a.y, al, be) + h2v.y, 0.f),
                    fmaxf(fmaf(-a.z, al, be) + h2v.z, 0.f),
                    fmaxf(fmaf(-a.w, al, be) + h2v.w, 0.f));
            }
        }
        if (lane < 4) F4[140 + lane] = ZERO4;
        __syncwarp();

        // ---- FSUM = sum_i F4[i] (144 entries, pads zero) ----
        float4 fs;
        {
            fs = add4(add4(F4[lane], F4[lane + 32]), add4(F4[lane + 64], F4[lane + 96]));
            if (lane + 128 < 144) fs = add4(fs, F4[lane + 128]);
            fs = wred4(fs);
        }

        // ---- oa: min-identity (FMNMX on alu + FADD on fma) ----
        {
            float4 acc[5];
            #pragma unroll
            for (int s = 0; s < 5; s++) acc[s] = ZERO4;

            const int slots[5] = {lane, lane + 32, oa2, oa3, oa4};
            const float4* QA = (const float4*)g_qoa;

            #pragma unroll 5
            for (int i4 = 0; i4 < 35; i4++) {
                float4 u0 = F4[4 * i4 + 0];
                float4 u1 = F4[4 * i4 + 1];
                float4 u2 = F4[4 * i4 + 2];
                float4 u3 = F4[4 * i4 + 3];
                const float4* qrow = QA + i4 * 70;
                #pragma unroll
                for (int s = 0; s < 5; s++) {
                    float4 w = __ldg(qrow + slots[s]);
                    accm4(acc[s], u0, w.x);
                    accm4(acc[s], u1, w.y);
                    accm4(acc[s], u2, w.z);
                    accm4(acc[s], u3, w.w);
                }
            }
            __syncwarp();   // F reads done before A overwrite of X region

            const int js[5] = {lane, lane + 32, j2, j3, j4};
            const int ds[5] = {lane, lane + 32, d2, d3, d4};
            #pragma unroll
            for (int s = 0; s < 5; s++) {
                A4[ds[s]] = bnrelu4p(v2sa(acc[s], fs),
                                     s_small[AOAOFF + js[s]], s_small[BOAOFF + js[s]]);
            }
            if (lane < 2) {
                A4[70 + lane]  = ZERO4;
                A4[142 + lane] = ZERO4;
            }
        }
        __syncwarp();

        // ---- branch sums of A (72 float4 each, pads zero) ----
        float4 as0, as1;
        {
            float4 s0 = add4(A4[lane], A4[lane + 32]);
            if (lane + 64 < 72) s0 = add4(s0, A4[lane + 64]);
            float4 s1 = add4(A4[72 + lane], A4[72 + lane + 32]);
            if (lane + 64 < 72) s1 = add4(s1, A4[72 + lane + 64]);
            s0 = wred4(s0);
            s1 = wred4(s1);
            as0 = (obb0 == 0) ? s0 : s1;
            as1 = s1;
        }

        // ---- ob: min-identity ----
        {
            float4 b0 = ZERO4;
            float4 b1 = ZERO4;
            const float4* QB = (const float4*)g_qob;
            const float4* a0p = A4 + obb0 * 72;
            const float4* a1p = A4 + 72;

            #pragma unroll 6
            for (int i4 = 0; i4 < 18; i4++) {
                float4 w0 = __ldg(QB + i4 * 30 + ob0);
                accm4(b0, a0p[4 * i4 + 0], w0.x);
                accm4(b0, a0p[4 * i4 + 1], w0.y);
                accm4(b0, a0p[4 * i4 + 2], w0.z);
                accm4(b0, a0p[4 * i4 + 3], w0.w);
                float4 w1 = __ldg(QB + i4 * 30 + ob1);
                accm4(b1, a1p[4 * i4 + 0], w1.x);
                accm4(b1, a1p[4 * i4 + 1], w1.y);
                accm4(b1, a1p[4 * i4 + 2], w1.z);
                accm4(b1, a1p[4 * i4 + 3], w1.w);
            }
            __syncwarp();   // A reads done before B overwrite of H2 region

            B4[obb0 * 32 + obc0] = bnrelu4p(v2sa(b0, as0),
                                            s_small[AOBOFF + lane], s_small[BOBOFF + lane]);
            B4[32 + (jb1 - 30)]  = bnrelu4p(v2sa(b1, as1),
                                            s_small[AOBOFF + jb1], s_small[BOBOFF + jb1]);
            if (lane < 2) {
                B4[30 + lane] = ZERO4;
                B4[62 + lane] = ZERO4;
            }
        }
        __syncwarp();

        // ---- oc: 8 reductions, classic |diff| ----
        {
            float w0 = s_small[QOCOFF + lane], w1 = s_small[QOCOFF + 32 + lane];
            float4 p0 = B4[lane];
            float4 p1 = B4[32 + lane];
            float vA0 = fabsf(fdiff(p0.x, w0)), vA1 = fabsf(fdiff(p0.y, w0));
            float vA2 = fabsf(fdiff(p0.z, w0)), vA3 = fabsf(fdiff(p0.w, w0));
            float vI0 = fabsf(fdiff(p1.x, w1)), vI1 = fabsf(fdiff(p1.y, w1));
            float vI2 = fabsf(fdiff(p1.z, w1)), vI3 = fabsf(fdiff(p1.w, w1));
            #pragma unroll
            for (int s = 16; s > 0; s >>= 1) {
                vA0 += __shfl_xor_sync(0xffffffffu, vA0, s);
                vA1 += __shfl_xor_sync(0xffffffffu, vA1, s);
                vA2 += __shfl_xor_sync(0xffffffffu, vA2, s);
                vA3 += __shfl_xor_sync(0xffffffffu, vA3, s);
                vI0 += __shfl_xor_sync(0xffffffffu, vI0, s);
                vI1 += __shfl_xor_sync(0xffffffffu, vI1, s);
                vI2 += __shfl_xor_sync(0xffffffffu, vI2, s);
                vI3 += __shfl_xor_sync(0xffffffffu, vI3, s);
            }
            if (lane == 0) {
                float aA = s_small[AOCOFF],     bA = s_small[BOCOFF];
                float aI = s_small[AOCOFF + 1], bI = s_small[BOCOFF + 1];
                float vA[4] = {vA0, vA1, vA2, vA3};
                float vI[4] = {vI0, vI1, vI2, vI3};
                #pragma unroll
                for (int i = 0; i < 4; i++) {
                    if (e0 + i < nB) {
                        out[e0 + i]      = fmaxf(fmaf(-vA[i], aA, bA), 0.f);
                        out[nB + e0 + i] = fmaxf(fmaf(-vI[i], aI, bI), 0.f);
                    }
                }
            }
        }
        __syncwarp();   // B reads done before next iteration overwrites
    }
}

// ---------------------------------------------------------------------------
extern "C" void kernel_launch(void* const* d_in, const int* in_sizes, int n_in,
                              void* d_out, int out_size)
{
    const float* x     = (const float*)d_in[0];
    const float* w1    = (const float*)d_in[1];
    const float* bn1   = (const float*)d_in[2];
    const float* w2    = (const float*)d_in[3];
    const float* bn2   = (const float*)d_in[4];
    const float* wr1   = (const float*)d_in[5];
    const float* bnr1  = (const float*)d_in[6];
    const float* wr2   = (const float*)d_in[7];
    const float* bnr2  = (const float*)d_in[8];
    const float* wo1a  = (const float*)d_in[9];
    const float* bno1a = (const float*)d_in[10];
    const float* wo1b  = (const float*)d_in[11];
    const float* bno1b = (const float*)d_in[12];
    const float* wo1c  = (const float*)d_in[13];
    const float* bno1c = (const float*)d_in[14];
    const float* wo2a  = (const float*)d_in[15];
    const float* bno2a = (const float*)d_in[16];
    const float* wo2b  = (const float*)d_in[17];
    const float* bno2b = (const float*)d_in[18];
    const float* wo2c  = (const float*)d_in[19];
    const float* bno2c = (const float*)d_in[20];

    const int nB = in_sizes[0] / 256;

    setup_kernel<<<11, 256>>>(w1, w2, wr1, wr2, wo1a, wo1b, wo1c, wo2a, wo2b, wo2c,
                              bn1, bn2, bnr1, bnr2, bno1a, bno1b, bno1c,
                              bno2a, bno2b, bno2c);
    taunet_main<<<512, 128>>>(x, (float*)d_out, nB);
}

// round 17
// speedup vs baseline: 1.3279x; 1.2832x over previous
#include <cuda_runtime.h>

// ============================================================================
// AdderNet TauNet R17: R14 (best) with 64-thread CTAs (finer SM balance),
// oa unroll 7. Classic |diff| everywhere; dual-position pre1+pre2;
// channel-fastest lane maps; position-major r1/r2.
// ============================================================================

#define EPSV 1e-5f

// ---- s_small layout (floats), compact ----
#define W1OFF   0      // 5 x 16
#define W2OFF   80     // 50 x 12
#define R1TOFF  680    // 10ci x 16
#define R2TOFF  840    // 10ci x 16
#define A1OFF   1000
#define B1OFF   1005
#define A2OFF   1010
#define B2OFF   1020
#define AR1OFF  1030
#define BR1OFF  1040
#define AR2OFF  1050
#define BR2OFF  1060
#define AOAOFF  1070   // 140
#define BOAOFF  1210   // 140
#define AOBOFF  1350   // 60
#define BOBOFF  1410   // 60
#define AOCOFF  1470   // 2
#define BOCOFF  1472   // 2
#define QOCOFF  1474   // 64
#define SMALL_N 1540

__device__ float g_small[1544];
__device__ float g_qoa[2 * 35 * 70 * 4];   // [branch][i/4][c][4]
__device__ float g_qob[2 * 18 * 30 * 4];

__device__ __forceinline__ float quantv(float w, float s) {
    float t = fminf(fmaxf(w / s, -127.f), 127.f);
    return rintf(t) * s;
}

__device__ __forceinline__ void fill_bn(const float* bn, int c, float* A, float* Bt) {
    for (int i = threadIdx.x; i < c; i += blockDim.x) {
        float g = bn[i], b = bn[c + i], m = bn[2 * c + i], v = bn[3 * c + i];
        float al = g * rsqrtf(v + EPSV);
        A[i] = al;
        Bt[i] = b - m * al;
    }
}

// ---------------------------------------------------------------------------
__global__ void setup_kernel(
    const float* __restrict__ w1,   const float* __restrict__ w2,
    const float* __restrict__ wr1,  const float* __restrict__ wr2,
    const float* __restrict__ wo1a, const float* __restrict__ wo1b, const float* __restrict__ wo1c,
    const float* __restrict__ wo2a, const float* __restrict__ wo2b, const float* __restrict__ wo2c,
    const float* __restrict__ bn1,  const float* __restrict__ bn2,
    const float* __restrict__ bnr1, const float* __restrict__ bnr2,
    const float* __restrict__ bno1a, const float* __restrict__ bno1b, const float* __restrict__ bno1c,
    const float* __restrict__ bno2a, const float* __restrict__ bno2b, const float* __restrict__ bno2c)
{
    const int blk = blockIdx.x, tid = threadIdx.x;
    if (blk < 10) {
        const float* w; int n;
        switch (blk) {
            case 0: w = w1;   n = 65;   break;
            case 1: w = w2;   n = 450;  break;
            case 2: w = wr1;  n = 100;  break;
            case 3: w = wr2;  n = 100;  break;
            case 4: w = wo1a; n = 9800; break;
            case 5: w = wo2a; n = 9800; break;
            case 6: w = wo1b; n = 2100; break;
            case 7: w = wo2b; n = 2100; break;
            case 8: w = wo1c; n = 30;   break;
            default: w = wo2c; n = 30;  break;
        }
        __shared__ float red[256];
        float m = 0.f;
        for (int i = tid; i < n; i += 256) m = fmaxf(m, fabsf(w[i]));
        red[tid] = m;
        __syncthreads();
        for (int s = 128; s > 0; s >>= 1) {
            if (tid < s) red[tid] = fmaxf(red[tid], red[tid + s]);
            __syncthreads();
        }
        const float s = red[0] / 127.f;

        if (blk == 0) {
            for (int j = tid; j < 80; j += 256) {
                int c = j >> 4, k = j & 15;
                g_small[W1OFF + j] = (k < 13) ? quantv(w[c * 13 + k], s) : 0.f;
            }
        } else if (blk == 1) {
            for (int j = tid; j < 600; j += 256) {
                int row = j / 12, k = j - row * 12;
                g_small[W2OFF + j] = (k < 9) ? quantv(w[row * 9 + k], s) : 0.f;
            }
        } else if (blk == 2 || blk == 3) {
            float* dst = g_small + (blk == 2 ? R1TOFF : R2TOFF);
            for (int j = tid; j < 160; j += 256) {
                int ci = j >> 4, rem = j & 15;
                int g = rem >> 3, k = rem & 7;
                int c = 5 * g + k;
                dst[j] = (k < 5) ? quantv(w[c * 10 + ci], s) : 0.f;
            }
        } else if (blk == 4 || blk == 5) {
            float* dst = g_qoa + (blk - 4) * 9800;
            for (int j = tid; j < 9800; j += 256) {
                int i4 = j / 280, rem = j - i4 * 280;
                int c = rem >> 2, t = rem & 3;
                dst[j] = quantv(w[c * 140 + i4 * 4 + t], s);
            }
        } else if (blk == 6 || blk == 7) {
            float* dst = g_qob + (blk - 6) * 2160;
            for (int j = tid; j < 2160; j += 256) {
                int i4 = j / 120, rem = j - i4 * 120;
                int c = rem >> 2, t = rem & 3;
                int i = i4 * 4 + t;
                dst[j] = (i < 70) ? quantv(w[c * 70 + i], s) : 0.f;
            }
        } else {
            float* dst = g_small + QOCOFF + (blk - 8) * 32;
            if (tid < 32) dst[tid] = (tid < 30) ? quantv(w[tid], s) : 0.f;
        }
    } else {
        fill_bn(bn1, 5,  g_small + A1OFF,  g_small + B1OFF);
        fill_bn(bn2, 10, g_small + A2OFF,  g_small + B2OFF);
        fill_bn(bnr1, 10, g_small + AR1OFF, g_small + BR1OFF);
        fill_bn(bnr2, 10, g_small + AR2OFF, g_small + BR2OFF);
        fill_bn(bno1a, 70, g_small + AOAOFF,      g_small + BOAOFF);
        fill_bn(bno2a, 70, g_small + AOAOFF + 70, g_small + BOAOFF + 70);
        fill_bn(bno1b, 30, g_small + AOBOFF,      g_small + BOBOFF);
        fill_bn(bno2b, 30, g_small + AOBOFF + 30, g_small + BOBOFF + 30);
        fill_bn(bno1c, 1, g_small + AOCOFF,     g_small + BOCOFF);
        fill_bn(bno2c, 1, g_small + AOCOFF + 1, g_small + BOCOFF + 1);
    }
}

// ---------------------------------------------------------------------------
// Per-warp workspace (floats), same aliasing map as R14.
#define XOFF  0
#define H1OFF 1024
#define H2OFF 2004
#define FOFF  1024
#define AOFF  0
#define BOFF  2004
#define WS_N  2580

__device__ __forceinline__ void ld4(float* d, const float* s) {
    float4 v = *(const float4*)s;
    d[0] = v.x; d[1] = v.y; d[2] = v.z; d[3] = v.w;
}

// d = u - w as FFMA-imm (bit-identical)
__device__ __forceinline__ float fdiff(float u, float w) {
    float d;
    asm("fma.rn.f32 %0, %1, 0fBF800000, %2;" : "=f"(d) : "f"(w), "f"(u));
    return d;
}

__device__ __forceinline__ void acc4(float4& a, float4 u, float w) {
    a.x += fabsf(fdiff(u.x, w));
    a.y += fabsf(fdiff(u.y, w));
    a.z += fabsf(fdiff(u.z, w));
    a.w += fabsf(fdiff(u.w, w));
}

__device__ __forceinline__ float4 add4(float4 a, float4 b) {
    return make_float4(a.x + b.x, a.y + b.y, a.z + b.z, a.w + b.w);
}

__device__ __forceinline__ float4 bnrelu4(float4 a, float al, float be) {
    return make_float4(fmaxf(fmaf(-a.x, al, be), 0.f),
                       fmaxf(fmaf(-a.y, al, be), 0.f),
                       fmaxf(fmaf(-a.z, al, be), 0.f),
                       fmaxf(fmaf(-a.w, al, be), 0.f));
}

#define ZERO4 make_float4(0.f, 0.f, 0.f, 0.f)

__global__ void __launch_bounds__(64) taunet_main(const float* __restrict__ x,
                                                  float* __restrict__ out, int nB)
{
    __shared__ __align__(16) float s_small[SMALL_N];
    __shared__ __align__(16) float s_ws[2][WS_N];

    for (int i = threadIdx.x; i < SMALL_N; i += 64) s_small[i] = g_small[i];
    __syncthreads();

    const int warp = threadIdx.x >> 5, lane = threadIdx.x & 31;
    float* ws = s_ws[warp];
    float4* X4  = (float4*)(ws + XOFF);
    float4* H14 = (float4*)(ws + H1OFF);
    float4* H24 = (float4*)(ws + H2OFF);
    float4* T4  = (float4*)(ws + XOFF);
    float4* F4  = (float4*)(ws + FOFF);
    float4* A4  = (float4*)(ws + AOFF);
    float4* B4  = (float4*)(ws + BOFF);

    // ---- per-lane o-layer slot precompute ----
    const int j2 = lane + 64, j3 = lane + 96;
    const int j4 = (lane + 128 < 140) ? lane + 128 : 139;
    const int oa2 = (j2 < 70) ? j2 : (2450 + (j2 - 70));
    const int oa3 = 2450 + (j3 - 70);
    const int oa4 = 2450 + (j4 - 70);
    const int d2 = (j2 < 70) ? j2 : (72 + (j2 - 70));
    const int d3 = 72 + (j3 - 70);
    const int d4 = 72 + (j4 - 70);
    const int jb1 = (lane + 32 < 60) ? lane + 32 : 59;
    const int obb0 = lane / 30, obc0 = lane - 30 * obb0;
    const int ob0 = obb0 * 540 + obc0;
    const int ob1 = 540 + (jb1 - 30);
    const int rp = lane >> 1, rg = lane & 1;

    const int nQ = (nB + 3) >> 2;
    const int gw = blockIdx.x * 2 + warp;
    const int stride = gridDim.x * 2;

    for (int q = gw; q < nQ; q += stride) {
        const int e0 = 4 * q;
        const int e1 = (e0 + 1 < nB) ? e0 + 1 : nB - 1;
        const int e2 = (e0 + 2 < nB) ? e0 + 2 : nB - 1;
        const int e3 = (e0 + 3 < nB) ? e0 + 3 : nB - 1;

        // ---- stage 4 input rows, transposed into float4-per-position ----
        {
            const float4* r0 = (const float4*)(x + (size_t)e0 * 256);
            const float4* r1 = (const float4*)(x + (size_t)e1 * 256);
            const float4* r2 = (const float4*)(x + (size_t)e2 * 256);
            const float4* r3 = (const float4*)(x + (size_t)e3 * 256);
            #pragma unroll
            for (int i = 0; i < 2; i++) {
                int m = lane + 32 * i;
                float4 a = __ldg(r0 + m);
                float4 b = __ldg(r1 + m);
                float4 c = __ldg(r2 + m);
                float4 d = __ldg(r3 + m);
                X4[4 * m + 0] = make_float4(a.x, b.x, c.x, d.x);
                X4[4 * m + 1] = make_float4(a.y, b.y, c.y, d.y);
                X4[4 * m + 2] = make_float4(a.z, b.z, c.z, d.z);
                X4[4 * m + 3] = make_float4(a.w, b.w, c.w, d.w);
            }
        }
        __syncwarp();

        // ---- pre1: 125 dual-position tasks, channel-fastest ----
        #pragma unroll 1
        for (int r = 0; r < 4; r++) {
            int idx = lane + 32 * r;
            if (idx < 125) {
                int pd = idx / 5, c = idx - 5 * pd;
                int p0 = 2 * pd;
                bool dual = (pd < 24);
                float w[16];
                const float* wb = s_small + W1OFF + c * 16;
                ld4(w, wb); ld4(w + 4, wb + 4); ld4(w + 8, wb + 8); ld4(w + 12, wb + 12);
                const float4* xp = X4 + 5 * p0;
                float4 A0 = ZERO4, B0 = ZERO4, A1 = ZERO4, B1 = ZERO4;
                #pragma unroll
                for (int k = 0; k < 13; k++) {
                    float4 a = xp[k];
                    if (k & 1) acc4(B0, a, w[k]); else acc4(A0, a, w[k]);
                    if (k >= 5) {
                        if ((k - 5) & 1) acc4(B1, a, w[k - 5]); else acc4(A1, a, w[k - 5]);
                    }
                }
                if (dual) {
                    #pragma unroll
                    for (int k = 13; k < 18; k++) {
                        float4 a = xp[k];
                        if ((k - 5) & 1) acc4(B1, a, w[k - 5]); else acc4(A1, a, w[k - 5]);
                    }
                }
                float al = s_small[A1OFF + c], be = s_small[B1OFF + c];
                H14[c * 49 + p0] = bnrelu4(add4(A0, B0), al, be);
                if (dual)
                    H14[c * 49 + p0 + 1] = bnrelu4(add4(A1, B1), al, be);
            }
        }
        __syncwarp();

        // ---- pre2: 70 dual-position tasks, channel-fastest ----
        #pragma unroll 1
        for (int r = 0; r < 3; r++) {
            int idx = lane + 32 * r;
            if (idx < 70) {
                int pd = idx / 10, c = idx - 10 * pd;
                int p0 = 2 * pd;
                const float4* hp = H14 + 3 * p0;
                float4 A0 = ZERO4, B0 = ZERO4, A1 = ZERO4, B1 = ZERO4;
                #pragma unroll
                for (int ci = 0; ci < 5; ci++) {
                    float w[12];
                    const float* wb = s_small + W2OFF + (c * 5 + ci) * 12;
                    ld4(w, wb); ld4(w + 4, wb + 4); ld4(w + 8, wb + 8);
                    const float4* hc = hp + ci * 49;
                    #pragma unroll
                    for (int k = 0; k < 12; k++) {
                        float4 a = hc[k];
                        if (k < 9) {
                            if (k & 1) acc4(B0, a, w[k]); else acc4(A0, a, w[k]);
                        }
                        if (k >= 3) {
                            if ((k - 3) & 1) acc4(B1, a, w[k - 3]); else acc4(A1, a, w[k - 3]);
                        }
                    }
                }
                float al = s_small[A2OFF + c], be = s_small[B2OFF + c];
                H24[c * 14 + p0]     = bnrelu4(add4(A0, B0), al, be);
                H24[c * 14 + p0 + 1] = bnrelu4(add4(A1, B1), al, be);
            }
        }
        __syncwarp();

        // ---- r1: position-major, lanes 0..27 = (p, g) ----
        if (lane < 28) {
            float4 acc[5];
            #pragma unroll
            for (int j = 0; j < 5; j++) acc[j] = ZERO4;
            const float* wt = s_small + R1TOFF + 8 * rg;
            #pragma unroll
            for (int ci = 0; ci < 10; ci++) {
                float4 a = H24[ci * 14 + rp];
                float w8[8];
                ld4(w8, wt + ci * 16); ld4(w8 + 4, wt + ci * 16 + 4);
                #pragma unroll
                for (int j = 0; j < 5; j++) acc4(acc[j], a, w8[j]);
            }
            #pragma unroll
            for (int j = 0; j < 5; j++) {
                int c = 5 * rg + j;
                T4[c * 14 + rp] = bnrelu4(acc[j], s_small[AR1OFF + c], s_small[BR1OFF + c]);
            }
        }
        __syncwarp();

        // ---- r2 + residual ----
        if (lane < 28) {
            float4 acc[5];
            #pragma unroll
            for (int j = 0; j < 5; j++) acc[j] = ZERO4;
            const float* wt = s_small + R2TOFF + 8 * rg;
            #pragma unroll
            for (int ci = 0; ci < 10; ci++) {
                float4 a = T4[ci * 14 + rp];
                float w8[8];
                ld4(w8, wt + ci * 16); ld4(w8 + 4, wt + ci * 16 + 4);
                #pragma unroll
                for (int j = 0; j < 5; j++) acc4(acc[j], a, w8[j]);
            }
            #pragma unroll
            for (int j = 0; j < 5; j++) {
                int c = 5 * rg + j;
                float al = s_small[AR2OFF + c], be = s_small[BR2OFF + c];
                float4 h2v = H24[c * 14 + rp];
                float4 a = acc[j];
                F4[c * 14 + rp] = make_float4(
                    fmaxf(fmaf(-a.x, al, be) + h2v.x, 0.f),
                    fmaxf(fmaf(-a.y, al, be) + h2v.y, 0.f),
                    fmaxf(fmaf(-a.z, al, be) + h2v.z, 0.f),
                    fmaxf(fmaf(-a.w, al, be) + h2v.w, 0.f));
            }
        }
        if (lane < 4) F4[140 + lane] = ZERO4;
        __syncwarp();

        // ---- oa: 5 channel slots x 4 packed elements ----
        {
            float4 acc[5];
            #pragma unroll
            for (int s = 0; s < 5; s++) acc[s] = ZERO4;

            const int slots[5] = {lane, lane + 32, oa2, oa3, oa4};
            const float4* QA = (const float4*)g_qoa;

            #pragma unroll 7
            for (int i4 = 0; i4 < 35; i4++) {
                float4 u0 = F4[4 * i4 + 0];
                float4 u1 = F4[4 * i4 + 1];
                float4 u2 = F4[4 * i4 + 2];
                float4 u3 = F4[4 * i4 + 3];
                const float4* qrow = QA + i4 * 70;
                #pragma unroll
                for (int s = 0; s < 5; s++) {
                    float4 w = __ldg(qrow + slots[s]);
                    acc4(acc[s], u0, w.x);
                    acc4(acc[s], u1, w.y);
                    acc4(acc[s], u2, w.z);
                    acc4(acc[s], u3, w.w);
                }
            }
            __syncwarp();   // F reads done before A overwrite of X region

            const int js[5] = {lane, lane + 32, j2, j3, j4};
            const int ds[5] = {lane, lane + 32, d2, d3, d4};
            #pragma unroll
            for (int s = 0; s < 5; s++) {
                A4[ds[s]] = bnrelu4(acc[s], s_small[AOAOFF + js[s]], s_small[BOAOFF + js[s]]);
            }
            if (lane < 2) {
                A4[70 + lane]  = ZERO4;
                A4[142 + lane] = ZERO4;
            }
        }
        __syncwarp();

        // ---- ob: 2 channel slots x 4 packed elements ----
        {
            float4 b0 = ZERO4;
            float4 b1 = ZERO4;
            const float4* QB = (const float4*)g_qob;
            const float4* a0p = A4 + obb0 * 72;
            const float4* a1p = A4 + 72;

            #pragma unroll 6
            for (int i4 = 0; i4 < 18; i4++) {
                float4 w0 = __ldg(QB + i4 * 30 + ob0);
                acc4(b0, a0p[4 * i4 + 0], w0.x);
                acc4(b0, a0p[4 * i4 + 1], w0.y);
                acc4(b0, a0p[4 * i4 + 2], w0.z);
                acc4(b0, a0p[4 * i4 + 3], w0.w);
                float4 w1 = __ldg(QB + i4 * 30 + ob1);
                acc4(b1, a1p[4 * i4 + 0], w1.x);
                acc4(b1, a1p[4 * i4 + 1], w1.y);
                acc4(b1, a1p[4 * i4 + 2], w1.z);
                acc4(b1, a1p[4 * i4 + 3], w1.w);
            }
            __syncwarp();   // A reads done before B overwrite of H2 region

            B4[obb0 * 32 + obc0] = bnrelu4(b0, s_small[AOBOFF + lane], s_small[BOBOFF + lane]);
            B4[32 + (jb1 - 30)]  = bnrelu4(b1, s_small[AOBOFF + jb1], s_small[BOBOFF + jb1]);
            if (lane < 2) {
                B4[30 + lane] = ZERO4;
                B4[62 + lane] = ZERO4;
            }
        }
        __syncwarp();

        // ---- oc: 8 reductions (4 elems x 2 branches) ----
        {
            float w0 = s_small[QOCOFF + lane], w1 = s_small[QOCOFF + 32 + lane];
            float4 p0 = B4[lane];
            float4 p1 = B4[32 + lane];
            float vA0 = fabsf(fdiff(p0.x, w0)), vA1 = fabsf(fdiff(p0.y, w0));
            float vA2 = fabsf(fdiff(p0.z, w0)), vA3 = fabsf(fdiff(p0.w, w0));
            float vI0 = fabsf(fdiff(p1.x, w1)), vI1 = fabsf(fdiff(p1.y, w1));
            float vI2 = fabsf(fdiff(p1.z, w1)), vI3 = fabsf(fdiff(p1.w, w1));
            #pragma unroll
            for (int s = 16; s > 0; s >>= 1) {
                vA0 += __shfl_xor_sync(0xffffffffu, vA0, s);
                vA1 += __shfl_xor_sync(0xffffffffu, vA1, s);
                vA2 += __shfl_xor_sync(0xffffffffu, vA2, s);
                vA3 += __shfl_xor_sync(0xffffffffu, vA3, s);
                vI0 += __shfl_xor_sync(0xffffffffu, vI0, s);
                vI1 += __shfl_xor_sync(0xffffffffu, vI1, s);
                vI2 += __shfl_xor_sync(0xffffffffu, vI2, s);
                vI3 += __shfl_xor_sync(0xffffffffu, vI3, s);
            }
            if (lane == 0) {
                float aA = s_small[AOCOFF],     bA = s_small[BOCOFF];
                float aI = s_small[AOCOFF + 1], bI = s_small[BOCOFF + 1];
                float vA[4] = {vA0, vA1, vA2, vA3};
                float vI[4] = {vI0, vI1, vI2, vI3};
                #pragma unroll
                for (int i = 0; i < 4; i++) {
                    if (e0 + i < nB) {
                        out[e0 + i]      = fmaxf(fmaf(-vA[i], aA, bA), 0.f);
                        out[nB + e0 + i] = fmaxf(fmaf(-vI[i], aI, bI), 0.f);
                    }
                }
            }
        }
        __syncwarp();   // B reads done before next iteration overwrites
    }
}

// ---------------------------------------------------------------------------
extern "C" void kernel_launch(void* const* d_in, const int* in_sizes, int n_in,
                              void* d_out, int out_size)
{
    const float* x     = (const float*)d_in[0];
    const float* w1    = (const float*)d_in[1];
    const float* bn1   = (const float*)d_in[2];
    const float* w2    = (const float*)d_in[3];
    const float* bn2   = (const float*)d_in[4];
    const float* wr1   = (const float*)d_in[5];
    const float* bnr1  = (const float*)d_in[6];
    const float* wr2   = (const float*)d_in[7];
    const float* bnr2  = (const float*)d_in[8];
    const float* wo1a  = (const float*)d_in[9];
    const float* bno1a = (const float*)d_in[10];
    const float* wo1b  = (const float*)d_in[11];
    const float* bno1b = (const float*)d_in[12];
    const float* wo1c  = (const float*)d_in[13];
    const float* bno1c = (const float*)d_in[14];
    const float* wo2a  = (const float*)d_in[15];
    const float* bno2a = (const float*)d_in[16];
    const float* wo2b  = (const float*)d_in[17];
    const float* bno2b = (const float*)d_in[18];
    const float* wo2c  = (const float*)d_in[19];
    const float* bno2c = (const float*)d_in[20];

    const int nB = in_sizes[0] / 256;
    const int nQ = (nB + 3) >> 2;
    const int grid = ((nQ + 1) >> 1) < 1024 ? ((nQ + 1) >> 1) : 1024;

    setup_kernel<<<11, 256>>>(w1, w2, wr1, wr2, wo1a, wo1b, wo1c, wo2a, wo2b, wo2c,
                              bn1, bn2, bnr1, bnr2, bno1a, bno1b, bno1c,
                              bno2a, bno2b, bno2c);
    taunet_main<<<grid, 64>>>(x, (float*)d_out, nB);
}